// round 13
// baseline (speedup 1.0000x reference)
#include <cuda_runtime.h>
#include <cuda_bf16.h>
#include <math.h>

#define BB   131072
#define TT   30
#define HH   150
#define GG   450      // 3*H
#define SDD  50
#define TB   32       // batch tile per CTA
#define NTH  352      // 10 gate warps + 1 MLP warp
#define JP   75       // j-pairs

// Device scratch for repacked weights (allowed: __device__ globals).
__device__ uint4  g_Wbf [HH * JP];       // bf16: (wr0,wz0|wr1,wz1|wn0,wn1|pad) [k][jp]
__device__ float2 g_Wih2[TT * GG];       // [t][j] -> (W_ih[j,2t], W_ih[j,2t+1])
__device__ float  g_W1p[HH * 80];        // [k][c<5][16]: W1[(10c+i)][k], i<10 (pad 16)

// ---------- packed fp32x2 FMA (sm_103a) ----------
__device__ __forceinline__ float2 ffma2(float2 a, float2 b, float2 c) {
    float2 r;
    asm("{\n\t"
        ".reg .b64 ra, rb, rc, rd;\n\t"
        "mov.b64 ra, {%2, %3};\n\t"
        "mov.b64 rb, {%4, %5};\n\t"
        "mov.b64 rc, {%6, %7};\n\t"
        "fma.rn.f32x2 rd, ra, rb, rc;\n\t"
        "mov.b64 {%0, %1}, rd;\n\t"
        "}"
        : "=f"(r.x), "=f"(r.y)
        : "f"(a.x), "f"(a.y), "f"(b.x), "f"(b.y), "f"(c.x), "f"(c.y));
    return r;
}

__device__ __forceinline__ float2 bflo2(unsigned u) {
    float f = __uint_as_float(u << 16);
    return make_float2(f, f);
}
__device__ __forceinline__ float2 bfhi2(unsigned u) {
    float f = __uint_as_float(u & 0xFFFF0000u);
    return make_float2(f, f);
}

__device__ __forceinline__ float tanh_hw(float x) {
    float y;
    asm("tanh.approx.f32 %0, %1;" : "=f"(y) : "f"(x));
    return y;
}
__device__ __forceinline__ float sigmf(float v) {
    return fmaf(0.5f, tanh_hw(0.5f * v), 0.5f);
}
__device__ __forceinline__ float softplusf(float v) {
    return fmaxf(v, 0.0f) + __logf(1.0f + __expf(-fabsf(v)));
}

__device__ __forceinline__ unsigned pack_bf16x2(float lo, float hi) {
    unsigned ulo = (unsigned)__bfloat16_as_ushort(__float2bfloat16_rn(lo));
    unsigned uhi = (unsigned)__bfloat16_as_ushort(__float2bfloat16_rn(hi));
    return (uhi << 16) | ulo;
}

#define BAR_SYNC(id, cnt)   asm volatile("bar.sync %0, %1;"   :: "r"(id), "r"(cnt) : "memory")
#define BAR_ARRIVE(id, cnt) asm volatile("bar.arrive %0, %1;" :: "r"(id), "r"(cnt) : "memory")

// ---------- setup: repack weights ----------
__global__ void repack_weights(const float* __restrict__ Whh,
                               const float* __restrict__ Wih,
                               const float* __restrict__ W1) {
    int idx = blockIdx.x * blockDim.x + threadIdx.x;
    if (idx < HH * JP) {            // -> g_Wbf [k][jp]
        int k = idx / JP, jp = idx % JP;
        int j0 = 2 * jp, j1 = 2 * jp + 1;
        uint4 w;
        w.x = pack_bf16x2(Whh[j0 * HH + k], Whh[(j0 + HH) * HH + k]);
        w.y = pack_bf16x2(Whh[j1 * HH + k], Whh[(j1 + HH) * HH + k]);
        w.z = pack_bf16x2(Whh[(j0 + 2 * HH) * HH + k],
                          Whh[(j1 + 2 * HH) * HH + k]);
        w.w = 0;
        g_Wbf[idx] = w;
    }
    if (idx < TT * GG) {            // -> g_Wih2[t][j]
        int t = idx / GG, j = idx % GG;
        g_Wih2[idx] = make_float2(Wih[j * (TT * 2) + 2 * t],
                                  Wih[j * (TT * 2) + 2 * t + 1]);
    }
    if (idx < HH * 80) {            // -> g_W1p[k][c][i], c<5, i<16 (10 used)
        int k = idx / 80, r = idx % 80;
        int c = r >> 4, i = r & 15;
        float v = 0.0f;
        if (i < 10) v = W1[(10 * c + i) * (HH + SDD) + k];
        g_W1p[idx] = v;
    }
}

// ---------- main fused recurrent kernel (warp-specialized) ----------
extern "C" __global__ void __launch_bounds__(NTH, 2)
r2p2_kernel(const float* __restrict__ stat,
            const float* __restrict__ init_v,
            const float* __restrict__ init_p,
            const float* __restrict__ zin,
            const float* __restrict__ b_ih,
            const float* __restrict__ b_hh,
            const float* __restrict__ W1,
            const float* __restrict__ b1,
            const float* __restrict__ W2,
            const float* __restrict__ b2,
            float* __restrict__ out) {
    extern __shared__ float smem[];
    float* s_gi = smem;                    // GG*TB   (layout [j][b])
    float* s_h  = s_gi + GG * TB;          // HH*TB   (layout [k][b])
    float* s_sp = s_h  + HH * TB;          // SDD*TB  (static proj + b1)
    float* s_o1 = s_sp + SDD * TB;         // SDD*TB
    float* s_x  = s_o1 + SDD * TB;         // TB*2

    const int tid = threadIdx.x;
    const int b0  = blockIdx.x * TB;

    // ---- init (all 352 threads) ----
    for (int idx = tid; idx < HH * TB; idx += NTH) s_h[idx] = 0.0f;
    for (int idx = tid; idx < GG * TB; idx += NTH) s_gi[idx] = b_ih[idx >> 5];
    for (int idx = tid; idx < SDD * TB; idx += NTH) {
        int m = idx >> 5, b = idx & 31;
        float acc = b1[m];
        const float* wrow = W1 + m * (HH + SDD) + HH;
        const float* st   = stat + (size_t)(b0 + b) * SDD;
        #pragma unroll 5
        for (int d = 0; d < SDD; ++d) acc = fmaf(wrow[d], st[d], acc);
        s_sp[idx] = acc;
    }
    __syncthreads();

    const size_t SIG_OFF = (size_t)2 * TT * BB;
    const size_t X_OFF   = (size_t)6 * TT * BB;

    if (tid < 320) {
        // ================= GATE GROUP: phases A + B =================
        const bool actA = (tid < 300);
        const int jp = tid >> 2;
        const int j0 = 2 * jp;
        const int qq = tid & 3;

        float bhr0 = 0.f, bhz0 = 0.f, bhn0 = 0.f;
        float bhr1 = 0.f, bhz1 = 0.f, bhn1 = 0.f;
        if (actA) {
            bhr0 = b_hh[j0];          bhr1 = b_hh[j0 + 1];
            bhz0 = b_hh[j0 + HH];     bhz1 = b_hh[j0 + 1 + HH];
            bhn0 = b_hh[j0 + 2 * HH]; bhn1 = b_hh[j0 + 1 + 2 * HH];
        }

        for (int t = 0; t < TT; ++t) {
            // ----- Phase A: gh partials on h_{t-1} (bf16 W, depth-2 pipeline) -----
            float2 aR[2][4], aZ[2][4], aN[2][4];
            if (actA) {
                #pragma unroll
                for (int jj = 0; jj < 2; ++jj)
                    #pragma unroll
                    for (int v = 0; v < 4; ++v) {
                        aR[jj][v] = make_float2(0.f, 0.f);
                        aZ[jj][v] = make_float2(0.f, 0.f);
                        aN[jj][v] = make_float2(0.f, 0.f);
                    }
                const uint4* wp = g_Wbf + jp;
                const float4* hp4 = reinterpret_cast<const float4*>(s_h) + 2 * qq;

                auto consume = [&](uint4 w, const float4* hp) {
                    float4 hv0 = hp[0];
                    float4 hv1 = hp[1];
                    float2 h00 = make_float2(hv0.x, hv0.y);
                    float2 h01 = make_float2(hv0.z, hv0.w);
                    float2 h10 = make_float2(hv1.x, hv1.y);
                    float2 h11 = make_float2(hv1.z, hv1.w);
                    float2 wr0 = bflo2(w.x);
                    float2 wz0 = bfhi2(w.x);
                    float2 wr1 = bflo2(w.y);
                    float2 wz1 = bfhi2(w.y);
                    float2 wn0 = bflo2(w.z);
                    float2 wn1 = bfhi2(w.z);
                    aR[0][0] = ffma2(h00, wr0, aR[0][0]);
                    aR[0][1] = ffma2(h01, wr0, aR[0][1]);
                    aR[0][2] = ffma2(h10, wr0, aR[0][2]);
                    aR[0][3] = ffma2(h11, wr0, aR[0][3]);
                    aZ[0][0] = ffma2(h00, wz0, aZ[0][0]);
                    aZ[0][1] = ffma2(h01, wz0, aZ[0][1]);
                    aZ[0][2] = ffma2(h10, wz0, aZ[0][2]);
                    aZ[0][3] = ffma2(h11, wz0, aZ[0][3]);
                    aN[0][0] = ffma2(h00, wn0, aN[0][0]);
                    aN[0][1] = ffma2(h01, wn0, aN[0][1]);
                    aN[0][2] = ffma2(h10, wn0, aN[0][2]);
                    aN[0][3] = ffma2(h11, wn0, aN[0][3]);
                    aR[1][0] = ffma2(h00, wr1, aR[1][0]);
                    aR[1][1] = ffma2(h01, wr1, aR[1][1]);
                    aR[1][2] = ffma2(h10, wr1, aR[1][2]);
                    aR[1][3] = ffma2(h11, wr1, aR[1][3]);
                    aZ[1][0] = ffma2(h00, wz1, aZ[1][0]);
                    aZ[1][1] = ffma2(h01, wz1, aZ[1][1]);
                    aZ[1][2] = ffma2(h10, wz1, aZ[1][2]);
                    aZ[1][3] = ffma2(h11, wz1, aZ[1][3]);
                    aN[1][0] = ffma2(h00, wn1, aN[1][0]);
                    aN[1][1] = ffma2(h01, wn1, aN[1][1]);
                    aN[1][2] = ffma2(h10, wn1, aN[1][2]);
                    aN[1][3] = ffma2(h11, wn1, aN[1][3]);
                };

                uint4 wA = __ldg(wp);
                uint4 wB = __ldg(wp + JP);
                wp += 2 * JP;
                #pragma unroll 1
                for (int k = 0; k < HH - 2; k += 2) {
                    uint4 wC = __ldg(wp);
                    uint4 wD = __ldg(wp + JP);
                    wp += 2 * JP;
                    consume(wA, hp4);  hp4 += 8;
                    consume(wB, hp4);  hp4 += 8;
                    wA = wC;
                    wB = wD;
                }
                consume(wA, hp4);  hp4 += 8;
                consume(wB, hp4);
            }
            BAR_SYNC(3, 320);            // all gate reads of h_{t-1} done
            if (t > 0) BAR_SYNC(2, NTH); // MLP finished C(t-1)/D2(t-1): h free, x ready

            // ----- Phase B (fused E): gi += Wih(:,t-1)*x_{t-1}; gates; h_t -----
            if (actA) {
                float2 wirA = make_float2(0.f, 0.f), wizA = wirA, winA = wirA;
                float2 wirB = wirA, wizB = wirA, winB = wirA;
                if (t > 0) {
                    const float2* wt = g_Wih2 + (t - 1) * GG;
                    wirA = __ldg(wt + j0);           wirB = __ldg(wt + j0 + 1);
                    wizA = __ldg(wt + j0 + HH);      wizB = __ldg(wt + j0 + 1 + HH);
                    winA = __ldg(wt + j0 + 2 * HH);  winB = __ldg(wt + j0 + 1 + 2 * HH);
                }
                float4* gi4 = reinterpret_cast<float4*>(s_gi);
                float4* h4 = reinterpret_cast<float4*>(s_h);
                const float4* sx4 = reinterpret_cast<const float4*>(s_x);
                #pragma unroll
                for (int jj = 0; jj < 2; ++jj) {
                    int j = j0 + jj;
                    float bhr = jj ? bhr1 : bhr0;
                    float bhz = jj ? bhz1 : bhz0;
                    float bhn = jj ? bhn1 : bhn0;
                    float2 wir = jj ? wirB : wirA;
                    float2 wiz = jj ? wizB : wizA;
                    float2 win = jj ? winB : winA;
                    #pragma unroll
                    for (int s = 0; s < 2; ++s) {
                        int fq = 2 * qq + s;
                        float4 vr = gi4[(j) * 8 + fq];
                        float4 vz = gi4[(j + HH) * 8 + fq];
                        float4 vn = gi4[(j + 2 * HH) * 8 + fq];
                        if (t > 0) {
                            float4 xa = sx4[2 * fq];
                            float4 xb = sx4[2 * fq + 1];
                            vr.x = fmaf(wir.x, xa.x, fmaf(wir.y, xa.y, vr.x));
                            vr.y = fmaf(wir.x, xa.z, fmaf(wir.y, xa.w, vr.y));
                            vr.z = fmaf(wir.x, xb.x, fmaf(wir.y, xb.y, vr.z));
                            vr.w = fmaf(wir.x, xb.z, fmaf(wir.y, xb.w, vr.w));
                            vz.x = fmaf(wiz.x, xa.x, fmaf(wiz.y, xa.y, vz.x));
                            vz.y = fmaf(wiz.x, xa.z, fmaf(wiz.y, xa.w, vz.y));
                            vz.z = fmaf(wiz.x, xb.x, fmaf(wiz.y, xb.y, vz.z));
                            vz.w = fmaf(wiz.x, xb.z, fmaf(wiz.y, xb.w, vz.w));
                            vn.x = fmaf(win.x, xa.x, fmaf(win.y, xa.y, vn.x));
                            vn.y = fmaf(win.x, xa.z, fmaf(win.y, xa.w, vn.y));
                            vn.z = fmaf(win.x, xb.x, fmaf(win.y, xb.y, vn.z));
                            vn.w = fmaf(win.x, xb.z, fmaf(win.y, xb.w, vn.w));
                            gi4[(j) * 8 + fq]          = vr;
                            gi4[(j + HH) * 8 + fq]     = vz;
                            gi4[(j + 2 * HH) * 8 + fq] = vn;
                        }
                        float2 aR0 = aR[jj][2*s], aR1 = aR[jj][2*s+1];
                        float2 aZ0 = aZ[jj][2*s], aZ1 = aZ[jj][2*s+1];
                        float2 aN0 = aN[jj][2*s], aN1 = aN[jj][2*s+1];
                        float r0 = sigmf(vr.x + aR0.x + bhr);
                        float r1 = sigmf(vr.y + aR0.y + bhr);
                        float r2 = sigmf(vr.z + aR1.x + bhr);
                        float r3 = sigmf(vr.w + aR1.y + bhr);
                        float z0 = sigmf(vz.x + aZ0.x + bhz);
                        float z1 = sigmf(vz.y + aZ0.y + bhz);
                        float z2 = sigmf(vz.z + aZ1.x + bhz);
                        float z3 = sigmf(vz.w + aZ1.y + bhz);
                        float n0 = tanh_hw(fmaf(r0, aN0.x + bhn, vn.x));
                        float n1 = tanh_hw(fmaf(r1, aN0.y + bhn, vn.y));
                        float n2 = tanh_hw(fmaf(r2, aN1.x + bhn, vn.z));
                        float n3 = tanh_hw(fmaf(r3, aN1.y + bhn, vn.w));
                        float4 hold = h4[j * 8 + fq];
                        float4 hnew;
                        hnew.x = fmaf(z0, hold.x - n0, n0);
                        hnew.y = fmaf(z1, hold.y - n1, n1);
                        hnew.z = fmaf(z2, hold.z - n2, n2);
                        hnew.w = fmaf(z3, hold.w - n3, n3);
                        h4[j * 8 + fq] = hnew;
                    }
                }
            }
            __threadfence_block();
            BAR_ARRIVE(1, NTH);          // h_t published to MLP warp
            BAR_SYNC(3, 320);            // gate-internal: h_t writes visible for A(t+1)
        }
    } else {
        // ================= MLP WARP: phases C + D1 + D2 =================
        const int lane = tid - 320;      // 0..31
        const int bp = lane >> 1;        // batch float2-pair 0..15
        const int kh = lane & 1;         // k half

        float xp0 = 0.f, xp1 = 0.f, dx0 = 0.f, dx1 = 0.f;
        {
            size_t g = (size_t)(b0 + lane) * 2;
            xp0 = init_p[g]; xp1 = init_p[g + 1];
            dx0 = init_v[g]; dx1 = init_v[g + 1];
        }

        for (int t = 0; t < TT; ++t) {
            BAR_SYNC(1, NTH);            // wait for h_t

            // ----- Phase C: o1 = softplus(h_t @ W1h^T + s_proj), 5 chunks of 10 m -----
            #pragma unroll 1
            for (int c = 0; c < 5; ++c) {
                float2 acc[10];
                #pragma unroll
                for (int i = 0; i < 10; ++i) acc[i] = make_float2(0.f, 0.f);
                const float2* hcol = reinterpret_cast<const float2*>(s_h)
                                     + kh * 75 * 16 + bp;
                const float* wb = g_W1p + kh * 75 * 80 + c * 16;
                #pragma unroll 3
                for (int kk = 0; kk < 75; ++kk) {
                    float2 hv = hcol[kk * 16];
                    float4 wa = __ldg(reinterpret_cast<const float4*>(wb));
                    float4 wc = __ldg(reinterpret_cast<const float4*>(wb + 4));
                    float2 we = __ldg(reinterpret_cast<const float2*>(wb + 8));
                    wb += 80;
                    acc[0] = ffma2(hv, make_float2(wa.x, wa.x), acc[0]);
                    acc[1] = ffma2(hv, make_float2(wa.y, wa.y), acc[1]);
                    acc[2] = ffma2(hv, make_float2(wa.z, wa.z), acc[2]);
                    acc[3] = ffma2(hv, make_float2(wa.w, wa.w), acc[3]);
                    acc[4] = ffma2(hv, make_float2(wc.x, wc.x), acc[4]);
                    acc[5] = ffma2(hv, make_float2(wc.y, wc.y), acc[5]);
                    acc[6] = ffma2(hv, make_float2(wc.z, wc.z), acc[6]);
                    acc[7] = ffma2(hv, make_float2(wc.w, wc.w), acc[7]);
                    acc[8] = ffma2(hv, make_float2(we.x, we.x), acc[8]);
                    acc[9] = ffma2(hv, make_float2(we.y, we.y), acc[9]);
                }
                #pragma unroll
                for (int i = 0; i < 10; ++i) {
                    acc[i].x += __shfl_xor_sync(0xFFFFFFFF, acc[i].x, 1);
                    acc[i].y += __shfl_xor_sync(0xFFFFFFFF, acc[i].y, 1);
                }
                if (kh == 0) {
                    #pragma unroll
                    for (int i = 0; i < 10; ++i) {
                        int m = 10 * c + i;
                        float2 sp = reinterpret_cast<const float2*>(s_sp)[m * 16 + bp];
                        s_o1[m * TB + 2 * bp]     = softplusf(acc[i].x + sp.x);
                        s_o1[m * TB + 2 * bp + 1] = softplusf(acc[i].y + sp.y);
                    }
                }
            }
            __syncwarp();

            // ----- Phase D1: o2 = softplus(o1 @ W2^T + b2), per-lane (b = lane) -----
            float o2[6];
            #pragma unroll
            for (int m = 0; m < 6; ++m) {
                float acc = b2[m];
                const float* w = W2 + m * SDD;
                #pragma unroll 5
                for (int k = 0; k < SDD; ++k)
                    acc = fmaf(w[k], s_o1[k * TB + lane], acc);
                o2[m] = softplusf(acc);
            }

            // ----- Phase D2: expm 2x2, x update, outputs -----
            {
                const int gb = b0 + lane;
                float aS = 2.0f * o2[2];
                float bS = o2[3] + o2[4];
                float cS = 2.0f * o2[5];
                float half_tr   = 0.5f * (aS + cS);
                float half_diff = 0.5f * (aS - cS);
                float disc = sqrtf(fmaf(half_diff, half_diff, bS * bS));
                float d = fmaxf(disc, 1e-12f);
                float ed  = __expf(d);
                float edi = __fdividef(1.0f, ed);
                float sinhc = __fdividef(0.5f * (ed - edi), d);
                float coshd = 0.5f * (ed + edi);
                if (disc < 1e-12f) coshd = 1.0f;
                float scale = __expf(half_tr);
                float m00 = scale * fmaf(sinhc,  half_diff, coshd);
                float m11 = scale * fmaf(-sinhc, half_diff, coshd);
                float m01 = scale * (sinhc * bS);

                float mu0 = xp0 + dx0 + o2[0];
                float mu1 = xp1 + dx1 + o2[1];
                float2 zv = reinterpret_cast<const float2*>(zin)[(size_t)t * BB + gb];
                float x0 = fmaf(m00, zv.x, fmaf(m01, zv.y, mu0));
                float x1 = fmaf(m01, zv.x, fmaf(m11, zv.y, mu1));
                dx0 = x0 - xp0; dx1 = x1 - xp1;
                xp0 = x0;       xp1 = x1;

                reinterpret_cast<float2*>(out)[(size_t)t * BB + gb] = make_float2(mu0, mu1);
                reinterpret_cast<float4*>(out + SIG_OFF)[(size_t)t * BB + gb] =
                    make_float4(m00, m01, m01, m11);
                reinterpret_cast<float2*>(out + X_OFF)[(size_t)t * BB + gb] = make_float2(x0, x1);
                s_x[2 * lane]     = x0;
                s_x[2 * lane + 1] = x1;
            }
            __threadfence_block();
            BAR_ARRIVE(2, NTH);          // x_t published; h_t readers done
        }
    }
}

extern "C" void kernel_launch(void* const* d_in, const int* in_sizes, int n_in,
                              void* d_out, int out_size) {
    const float* stat   = (const float*)d_in[0];
    const float* init_v = (const float*)d_in[1];
    const float* init_p = (const float*)d_in[2];
    const float* z      = (const float*)d_in[3];
    const float* W_ih   = (const float*)d_in[4];
    const float* W_hh   = (const float*)d_in[5];
    const float* b_ih   = (const float*)d_in[6];
    const float* b_hh   = (const float*)d_in[7];
    const float* W1     = (const float*)d_in[8];
    const float* b1     = (const float*)d_in[9];
    const float* W2     = (const float*)d_in[10];
    const float* b2     = (const float*)d_in[11];
    float* out = (float*)d_out;

    repack_weights<<<(TT * GG + 255) / 256, 256>>>(W_hh, W_ih, W1);

    const size_t smem_bytes =
        (size_t)(GG * TB + HH * TB + SDD * TB * 2 + TB * 2) * sizeof(float);
    cudaFuncSetAttribute(r2p2_kernel,
                         cudaFuncAttributeMaxDynamicSharedMemorySize,
                         (int)smem_bytes);
    r2p2_kernel<<<BB / TB, NTH, smem_bytes>>>(
        stat, init_v, init_p, z, b_ih, b_hh, W1, b1, W2, b2, out);
}

// round 14
// speedup vs baseline: 1.3134x; 1.3134x over previous
#include <cuda_runtime.h>
#include <cuda_bf16.h>
#include <math.h>

#define BB   131072
#define TT   30
#define HH   150
#define GG   450      // 3*H
#define SDD  50
#define TB   32       // batch tile per CTA
#define NTH  352      // 10 gate warps + 1 MLP warp
#define JP   75       // j-pairs

// Device scratch for repacked weights (allowed: __device__ globals).
__device__ uint4  g_Wbf [HH * JP];       // bf16: (wr0,wz0|wr1,wz1|wn0,wn1|pad) [k][jp]
__device__ float2 g_Wih2[TT * GG];       // [t][j] -> (W_ih[j,2t], W_ih[j,2t+1])

// ---------- packed fp32x2 FMA (sm_103a) ----------
__device__ __forceinline__ float2 ffma2(float2 a, float2 b, float2 c) {
    float2 r;
    asm("{\n\t"
        ".reg .b64 ra, rb, rc, rd;\n\t"
        "mov.b64 ra, {%2, %3};\n\t"
        "mov.b64 rb, {%4, %5};\n\t"
        "mov.b64 rc, {%6, %7};\n\t"
        "fma.rn.f32x2 rd, ra, rb, rc;\n\t"
        "mov.b64 {%0, %1}, rd;\n\t"
        "}"
        : "=f"(r.x), "=f"(r.y)
        : "f"(a.x), "f"(a.y), "f"(b.x), "f"(b.y), "f"(c.x), "f"(c.y));
    return r;
}

__device__ __forceinline__ float2 bflo2(unsigned u) {
    float f = __uint_as_float(u << 16);
    return make_float2(f, f);
}
__device__ __forceinline__ float2 bfhi2(unsigned u) {
    float f = __uint_as_float(u & 0xFFFF0000u);
    return make_float2(f, f);
}

__device__ __forceinline__ float tanh_hw(float x) {
    float y;
    asm("tanh.approx.f32 %0, %1;" : "=f"(y) : "f"(x));
    return y;
}
__device__ __forceinline__ float sigmf(float v) {
    return fmaf(0.5f, tanh_hw(0.5f * v), 0.5f);
}
__device__ __forceinline__ float softplusf(float v) {
    return fmaxf(v, 0.0f) + __logf(1.0f + __expf(-fabsf(v)));
}

__device__ __forceinline__ unsigned pack_bf16x2(float lo, float hi) {
    unsigned ulo = (unsigned)__bfloat16_as_ushort(__float2bfloat16_rn(lo));
    unsigned uhi = (unsigned)__bfloat16_as_ushort(__float2bfloat16_rn(hi));
    return (uhi << 16) | ulo;
}

#define BAR_SYNC(id, cnt)   asm volatile("bar.sync %0, %1;"   :: "r"(id), "r"(cnt) : "memory")
#define BAR_ARRIVE(id, cnt) asm volatile("bar.arrive %0, %1;" :: "r"(id), "r"(cnt) : "memory")

// ---------- setup: repack weights ----------
__global__ void repack_weights(const float* __restrict__ Whh,
                               const float* __restrict__ Wih) {
    int idx = blockIdx.x * blockDim.x + threadIdx.x;
    if (idx < HH * JP) {            // -> g_Wbf [k][jp]
        int k = idx / JP, jp = idx % JP;
        int j0 = 2 * jp, j1 = 2 * jp + 1;
        uint4 w;
        w.x = pack_bf16x2(Whh[j0 * HH + k], Whh[(j0 + HH) * HH + k]);
        w.y = pack_bf16x2(Whh[j1 * HH + k], Whh[(j1 + HH) * HH + k]);
        w.z = pack_bf16x2(Whh[(j0 + 2 * HH) * HH + k],
                          Whh[(j1 + 2 * HH) * HH + k]);
        w.w = 0;
        g_Wbf[idx] = w;
    }
    if (idx < TT * GG) {            // -> g_Wih2[t][j]
        int t = idx / GG, j = idx % GG;
        g_Wih2[idx] = make_float2(Wih[j * (TT * 2) + 2 * t],
                                  Wih[j * (TT * 2) + 2 * t + 1]);
    }
}

// ---------- main fused recurrent kernel (warp-specialized) ----------
extern "C" __global__ void __launch_bounds__(NTH, 2)
r2p2_kernel(const float* __restrict__ stat,
            const float* __restrict__ init_v,
            const float* __restrict__ init_p,
            const float* __restrict__ zin,
            const float* __restrict__ b_ih,
            const float* __restrict__ b_hh,
            const float* __restrict__ W1,
            const float* __restrict__ b1,
            const float* __restrict__ W2,
            const float* __restrict__ b2,
            float* __restrict__ out) {
    extern __shared__ float smem[];
    float* s_gi = smem;                       // GG*TB floats
    float* s_h  = s_gi + GG * TB;             // HH*TB
    float* s_sp = s_h  + HH * TB;             // SDD*TB  (static proj + b1)
    float* s_o1 = s_sp + SDD * TB;            // SDD*TB
    unsigned* s_w1u = reinterpret_cast<unsigned*>(s_o1 + SDD * TB); // HH*32 u32 (bf16 W1 hidden block)
    float* s_w2 = reinterpret_cast<float*>(s_w1u + HH * 32);       // 6*SDD
    float* s_x  = s_w2 + 6 * SDD;             // TB*2

    const int tid = threadIdx.x;
    const int b0  = blockIdx.x * TB;

    // ---- init (all 352 threads) ----
    for (int idx = tid; idx < HH * TB; idx += NTH) s_h[idx] = 0.0f;
    for (int idx = tid; idx < GG * TB; idx += NTH) s_gi[idx] = b_ih[idx >> 5];
    for (int idx = tid; idx < SDD * TB; idx += NTH) {
        int m = idx >> 5, b = idx & 31;
        float acc = b1[m];
        const float* wrow = W1 + m * (HH + SDD) + HH;
        const float* st   = stat + (size_t)(b0 + b) * SDD;
        #pragma unroll 5
        for (int d = 0; d < SDD; ++d) acc = fmaf(wrow[d], st[d], acc);
        s_sp[idx] = acc;
    }
    // W1 hidden block -> smem bf16: row k (32 u32), chunk c at c*6, pair q
    for (int idx = tid; idx < HH * 25; idx += NTH) {
        int k = idx / 25, p = idx % 25;
        int c = p / 5, q = p % 5;
        int m0 = 10 * c + 2 * q;
        s_w1u[k * 32 + c * 6 + q] =
            pack_bf16x2(W1[m0 * (HH + SDD) + k], W1[(m0 + 1) * (HH + SDD) + k]);
    }
    for (int idx = tid; idx < 6 * SDD; idx += NTH) s_w2[idx] = W2[idx];
    __syncthreads();

    const size_t SIG_OFF = (size_t)2 * TT * BB;
    const size_t X_OFF   = (size_t)6 * TT * BB;

    if (tid < 320) {
        // ================= GATE GROUP: phases A + B =================
        const bool actA = (tid < 300);
        const int jp = tid >> 2;
        const int j0 = 2 * jp;
        const int qq = tid & 3;

        float bhr0 = 0.f, bhz0 = 0.f, bhn0 = 0.f;
        float bhr1 = 0.f, bhz1 = 0.f, bhn1 = 0.f;
        if (actA) {
            bhr0 = b_hh[j0];          bhr1 = b_hh[j0 + 1];
            bhz0 = b_hh[j0 + HH];     bhz1 = b_hh[j0 + 1 + HH];
            bhn0 = b_hh[j0 + 2 * HH]; bhn1 = b_hh[j0 + 1 + 2 * HH];
        }

        for (int t = 0; t < TT; ++t) {
            // ----- Phase A: gh partials on h_{t-1} (bf16 W, depth-2 pipeline) -----
            float2 aR[2][4], aZ[2][4], aN[2][4];
            if (actA) {
                #pragma unroll
                for (int jj = 0; jj < 2; ++jj)
                    #pragma unroll
                    for (int v = 0; v < 4; ++v) {
                        aR[jj][v] = make_float2(0.f, 0.f);
                        aZ[jj][v] = make_float2(0.f, 0.f);
                        aN[jj][v] = make_float2(0.f, 0.f);
                    }
                const uint4* wp = g_Wbf + jp;
                const float4* hp4 = reinterpret_cast<const float4*>(s_h) + 2 * qq;

                auto consume = [&](uint4 w, const float4* hp) {
                    float4 hv0 = hp[0];
                    float4 hv1 = hp[1];
                    float2 h00 = make_float2(hv0.x, hv0.y);
                    float2 h01 = make_float2(hv0.z, hv0.w);
                    float2 h10 = make_float2(hv1.x, hv1.y);
                    float2 h11 = make_float2(hv1.z, hv1.w);
                    float2 wr0 = bflo2(w.x);
                    float2 wz0 = bfhi2(w.x);
                    float2 wr1 = bflo2(w.y);
                    float2 wz1 = bfhi2(w.y);
                    float2 wn0 = bflo2(w.z);
                    float2 wn1 = bfhi2(w.z);
                    aR[0][0] = ffma2(h00, wr0, aR[0][0]);
                    aR[0][1] = ffma2(h01, wr0, aR[0][1]);
                    aR[0][2] = ffma2(h10, wr0, aR[0][2]);
                    aR[0][3] = ffma2(h11, wr0, aR[0][3]);
                    aZ[0][0] = ffma2(h00, wz0, aZ[0][0]);
                    aZ[0][1] = ffma2(h01, wz0, aZ[0][1]);
                    aZ[0][2] = ffma2(h10, wz0, aZ[0][2]);
                    aZ[0][3] = ffma2(h11, wz0, aZ[0][3]);
                    aN[0][0] = ffma2(h00, wn0, aN[0][0]);
                    aN[0][1] = ffma2(h01, wn0, aN[0][1]);
                    aN[0][2] = ffma2(h10, wn0, aN[0][2]);
                    aN[0][3] = ffma2(h11, wn0, aN[0][3]);
                    aR[1][0] = ffma2(h00, wr1, aR[1][0]);
                    aR[1][1] = ffma2(h01, wr1, aR[1][1]);
                    aR[1][2] = ffma2(h10, wr1, aR[1][2]);
                    aR[1][3] = ffma2(h11, wr1, aR[1][3]);
                    aZ[1][0] = ffma2(h00, wz1, aZ[1][0]);
                    aZ[1][1] = ffma2(h01, wz1, aZ[1][1]);
                    aZ[1][2] = ffma2(h10, wz1, aZ[1][2]);
                    aZ[1][3] = ffma2(h11, wz1, aZ[1][3]);
                    aN[1][0] = ffma2(h00, wn1, aN[1][0]);
                    aN[1][1] = ffma2(h01, wn1, aN[1][1]);
                    aN[1][2] = ffma2(h10, wn1, aN[1][2]);
                    aN[1][3] = ffma2(h11, wn1, aN[1][3]);
                };

                uint4 wA = __ldg(wp);
                uint4 wB = __ldg(wp + JP);
                wp += 2 * JP;
                #pragma unroll 1
                for (int k = 0; k < HH - 2; k += 2) {
                    uint4 wC = __ldg(wp);
                    uint4 wD = __ldg(wp + JP);
                    wp += 2 * JP;
                    consume(wA, hp4);  hp4 += 8;
                    consume(wB, hp4);  hp4 += 8;
                    wA = wC;
                    wB = wD;
                }
                consume(wA, hp4);  hp4 += 8;
                consume(wB, hp4);
            }
            BAR_SYNC(3, 320);            // all gate reads of h_{t-1} done
            if (t > 0) BAR_SYNC(2, NTH); // MLP finished C(t-1)/D2(t-1): h free, x ready

            // ----- Phase B (fused E): gi += Wih(:,t-1)*x_{t-1}; gates; h_t -----
            if (actA) {
                float2 wirA = make_float2(0.f, 0.f), wizA = wirA, winA = wirA;
                float2 wirB = wirA, wizB = wirA, winB = wirA;
                if (t > 0) {
                    const float2* wt = g_Wih2 + (t - 1) * GG;
                    wirA = __ldg(wt + j0);           wirB = __ldg(wt + j0 + 1);
                    wizA = __ldg(wt + j0 + HH);      wizB = __ldg(wt + j0 + 1 + HH);
                    winA = __ldg(wt + j0 + 2 * HH);  winB = __ldg(wt + j0 + 1 + 2 * HH);
                }
                float4* gi4 = reinterpret_cast<float4*>(s_gi);
                float4* h4 = reinterpret_cast<float4*>(s_h);
                const float4* sx4 = reinterpret_cast<const float4*>(s_x);
                #pragma unroll
                for (int jj = 0; jj < 2; ++jj) {
                    int j = j0 + jj;
                    float bhr = jj ? bhr1 : bhr0;
                    float bhz = jj ? bhz1 : bhz0;
                    float bhn = jj ? bhn1 : bhn0;
                    float2 wir = jj ? wirB : wirA;
                    float2 wiz = jj ? wizB : wizA;
                    float2 win = jj ? winB : winA;
                    #pragma unroll
                    for (int s = 0; s < 2; ++s) {
                        int fq = 2 * qq + s;
                        float4 vr = gi4[(j) * 8 + fq];
                        float4 vz = gi4[(j + HH) * 8 + fq];
                        float4 vn = gi4[(j + 2 * HH) * 8 + fq];
                        if (t > 0) {
                            float4 xa = sx4[2 * fq];
                            float4 xb = sx4[2 * fq + 1];
                            vr.x = fmaf(wir.x, xa.x, fmaf(wir.y, xa.y, vr.x));
                            vr.y = fmaf(wir.x, xa.z, fmaf(wir.y, xa.w, vr.y));
                            vr.z = fmaf(wir.x, xb.x, fmaf(wir.y, xb.y, vr.z));
                            vr.w = fmaf(wir.x, xb.z, fmaf(wir.y, xb.w, vr.w));
                            vz.x = fmaf(wiz.x, xa.x, fmaf(wiz.y, xa.y, vz.x));
                            vz.y = fmaf(wiz.x, xa.z, fmaf(wiz.y, xa.w, vz.y));
                            vz.z = fmaf(wiz.x, xb.x, fmaf(wiz.y, xb.y, vz.z));
                            vz.w = fmaf(wiz.x, xb.z, fmaf(wiz.y, xb.w, vz.w));
                            vn.x = fmaf(win.x, xa.x, fmaf(win.y, xa.y, vn.x));
                            vn.y = fmaf(win.x, xa.z, fmaf(win.y, xa.w, vn.y));
                            vn.z = fmaf(win.x, xb.x, fmaf(win.y, xb.y, vn.z));
                            vn.w = fmaf(win.x, xb.z, fmaf(win.y, xb.w, vn.w));
                            gi4[(j) * 8 + fq]          = vr;
                            gi4[(j + HH) * 8 + fq]     = vz;
                            gi4[(j + 2 * HH) * 8 + fq] = vn;
                        }
                        float2 aR0 = aR[jj][2*s], aR1 = aR[jj][2*s+1];
                        float2 aZ0 = aZ[jj][2*s], aZ1 = aZ[jj][2*s+1];
                        float2 aN0 = aN[jj][2*s], aN1 = aN[jj][2*s+1];
                        float r0 = sigmf(vr.x + aR0.x + bhr);
                        float r1 = sigmf(vr.y + aR0.y + bhr);
                        float r2 = sigmf(vr.z + aR1.x + bhr);
                        float r3 = sigmf(vr.w + aR1.y + bhr);
                        float z0 = sigmf(vz.x + aZ0.x + bhz);
                        float z1 = sigmf(vz.y + aZ0.y + bhz);
                        float z2 = sigmf(vz.z + aZ1.x + bhz);
                        float z3 = sigmf(vz.w + aZ1.y + bhz);
                        float n0 = tanh_hw(fmaf(r0, aN0.x + bhn, vn.x));
                        float n1 = tanh_hw(fmaf(r1, aN0.y + bhn, vn.y));
                        float n2 = tanh_hw(fmaf(r2, aN1.x + bhn, vn.z));
                        float n3 = tanh_hw(fmaf(r3, aN1.y + bhn, vn.w));
                        float4 hold = h4[j * 8 + fq];
                        float4 hnew;
                        hnew.x = fmaf(z0, hold.x - n0, n0);
                        hnew.y = fmaf(z1, hold.y - n1, n1);
                        hnew.z = fmaf(z2, hold.z - n2, n2);
                        hnew.w = fmaf(z3, hold.w - n3, n3);
                        h4[j * 8 + fq] = hnew;
                    }
                }
            }
            __threadfence_block();
            BAR_ARRIVE(1, NTH);          // h_t published to MLP warp
            BAR_SYNC(3, 320);            // gate-internal: h_t writes visible for A(t+1)
        }
    } else {
        // ================= MLP WARP: phases C + D1 + D2 =================
        const int lane = tid - 320;      // 0..31
        const int bp = lane >> 1;        // batch float2-pair 0..15
        const int kh = lane & 1;         // k half

        float xp0 = 0.f, xp1 = 0.f, dx0 = 0.f, dx1 = 0.f;
        {
            size_t g = (size_t)(b0 + lane) * 2;
            xp0 = init_p[g]; xp1 = init_p[g + 1];
            dx0 = init_v[g]; dx1 = init_v[g + 1];
        }

        for (int t = 0; t < TT; ++t) {
            BAR_SYNC(1, NTH);            // wait for h_t

            // ----- Phase C: o1 = softplus(h_t @ W1h^T + s_proj), 5 chunks of 10 m -----
            // W1 weights from SMEM (bf16 pairs), broadcast across bp lanes.
            #pragma unroll 1
            for (int c = 0; c < 5; ++c) {
                float2 acc[10];
                #pragma unroll
                for (int i = 0; i < 10; ++i) acc[i] = make_float2(0.f, 0.f);
                const float2* hcol = reinterpret_cast<const float2*>(s_h)
                                     + kh * 75 * 16 + bp;
                const unsigned* wp = s_w1u + kh * 75 * 32 + c * 6;
                #pragma unroll 3
                for (int kk = 0; kk < 75; ++kk) {
                    float2 hv = hcol[kk * 16];
                    uint2 wa = *reinterpret_cast<const uint2*>(wp);
                    uint2 wb = *reinterpret_cast<const uint2*>(wp + 2);
                    unsigned wc = wp[4];
                    wp += 32;
                    acc[0] = ffma2(hv, bflo2(wa.x), acc[0]);
                    acc[1] = ffma2(hv, bfhi2(wa.x), acc[1]);
                    acc[2] = ffma2(hv, bflo2(wa.y), acc[2]);
                    acc[3] = ffma2(hv, bfhi2(wa.y), acc[3]);
                    acc[4] = ffma2(hv, bflo2(wb.x), acc[4]);
                    acc[5] = ffma2(hv, bfhi2(wb.x), acc[5]);
                    acc[6] = ffma2(hv, bflo2(wb.y), acc[6]);
                    acc[7] = ffma2(hv, bfhi2(wb.y), acc[7]);
                    acc[8] = ffma2(hv, bflo2(wc),   acc[8]);
                    acc[9] = ffma2(hv, bfhi2(wc),   acc[9]);
                }
                #pragma unroll
                for (int i = 0; i < 10; ++i) {
                    acc[i].x += __shfl_xor_sync(0xFFFFFFFF, acc[i].x, 1);
                    acc[i].y += __shfl_xor_sync(0xFFFFFFFF, acc[i].y, 1);
                }
                if (kh == 0) {
                    #pragma unroll
                    for (int i = 0; i < 10; ++i) {
                        int m = 10 * c + i;
                        float2 sp = reinterpret_cast<const float2*>(s_sp)[m * 16 + bp];
                        s_o1[m * TB + 2 * bp]     = softplusf(acc[i].x + sp.x);
                        s_o1[m * TB + 2 * bp + 1] = softplusf(acc[i].y + sp.y);
                    }
                }
            }
            __syncwarp();

            // ----- Phase D1: o2 = softplus(o1 @ W2^T + b2), per-lane (b = lane) -----
            float o2[6];
            #pragma unroll
            for (int m = 0; m < 6; ++m) {
                float acc = b2[m];
                const float* w = s_w2 + m * SDD;
                #pragma unroll 5
                for (int k = 0; k < SDD; ++k)
                    acc = fmaf(w[k], s_o1[k * TB + lane], acc);
                o2[m] = softplusf(acc);
            }

            // ----- Phase D2: expm 2x2, x update, outputs -----
            {
                const int gb = b0 + lane;
                float aS = 2.0f * o2[2];
                float bS = o2[3] + o2[4];
                float cS = 2.0f * o2[5];
                float half_tr   = 0.5f * (aS + cS);
                float half_diff = 0.5f * (aS - cS);
                float disc = sqrtf(fmaf(half_diff, half_diff, bS * bS));
                float d = fmaxf(disc, 1e-12f);
                float ed  = __expf(d);
                float edi = __fdividef(1.0f, ed);
                float sinhc = __fdividef(0.5f * (ed - edi), d);
                float coshd = 0.5f * (ed + edi);
                if (disc < 1e-12f) coshd = 1.0f;
                float scale = __expf(half_tr);
                float m00 = scale * fmaf(sinhc,  half_diff, coshd);
                float m11 = scale * fmaf(-sinhc, half_diff, coshd);
                float m01 = scale * (sinhc * bS);

                float mu0 = xp0 + dx0 + o2[0];
                float mu1 = xp1 + dx1 + o2[1];
                float2 zv = reinterpret_cast<const float2*>(zin)[(size_t)t * BB + gb];
                float x0 = fmaf(m00, zv.x, fmaf(m01, zv.y, mu0));
                float x1 = fmaf(m01, zv.x, fmaf(m11, zv.y, mu1));
                dx0 = x0 - xp0; dx1 = x1 - xp1;
                xp0 = x0;       xp1 = x1;

                reinterpret_cast<float2*>(out)[(size_t)t * BB + gb] = make_float2(mu0, mu1);
                reinterpret_cast<float4*>(out + SIG_OFF)[(size_t)t * BB + gb] =
                    make_float4(m00, m01, m01, m11);
                reinterpret_cast<float2*>(out + X_OFF)[(size_t)t * BB + gb] = make_float2(x0, x1);
                s_x[2 * lane]     = x0;
                s_x[2 * lane + 1] = x1;
            }
            __threadfence_block();
            BAR_ARRIVE(2, NTH);          // x_t published; h_t readers done
        }
    }
}

extern "C" void kernel_launch(void* const* d_in, const int* in_sizes, int n_in,
                              void* d_out, int out_size) {
    const float* stat   = (const float*)d_in[0];
    const float* init_v = (const float*)d_in[1];
    const float* init_p = (const float*)d_in[2];
    const float* z      = (const float*)d_in[3];
    const float* W_ih   = (const float*)d_in[4];
    const float* W_hh   = (const float*)d_in[5];
    const float* b_ih   = (const float*)d_in[6];
    const float* b_hh   = (const float*)d_in[7];
    const float* W1     = (const float*)d_in[8];
    const float* b1     = (const float*)d_in[9];
    const float* W2     = (const float*)d_in[10];
    const float* b2     = (const float*)d_in[11];
    float* out = (float*)d_out;

    repack_weights<<<(TT * GG + 255) / 256, 256>>>(W_hh, W_ih);

    const size_t smem_bytes =
        (size_t)(GG * TB + HH * TB + SDD * TB * 2       // gi, h, sp, o1 (floats)
                 + HH * 32                               // W1 bf16 (u32 slots)
                 + 6 * SDD + TB * 2) * sizeof(float);
    cudaFuncSetAttribute(r2p2_kernel,
                         cudaFuncAttributeMaxDynamicSharedMemorySize,
                         (int)smem_bytes);
    r2p2_kernel<<<BB / TB, NTH, smem_bytes>>>(
        stat, init_v, init_p, z, b_ih, b_hh, W1, b1, W2, b2, out);
}

// round 16
// speedup vs baseline: 1.4303x; 1.0890x over previous
#include <cuda_runtime.h>
#include <cuda_bf16.h>
#include <math.h>

#define BB   131072
#define TT   30
#define HH   150
#define GG   450      // 3*H
#define SDD  50
#define TB   32       // batch tile per CTA
#define NTH  320      // 10 warps; 300 active in GEMM phase
#define JP   75       // j-pairs

// Device scratch for repacked weights (allowed: __device__ globals).
__device__ uint4  g_Wbf [HH * JP];       // bf16: (wr0,wz0|wr1,wz1|wn0,wn1|pad) [k][jp]
__device__ float2 g_Wih2[TT * GG];       // [t][j] -> (W_ih[j,2t], W_ih[j,2t+1])

// ---------- packed fp32x2 FMA (sm_103a) ----------
__device__ __forceinline__ float2 ffma2(float2 a, float2 b, float2 c) {
    float2 r;
    asm("{\n\t"
        ".reg .b64 ra, rb, rc, rd;\n\t"
        "mov.b64 ra, {%2, %3};\n\t"
        "mov.b64 rb, {%4, %5};\n\t"
        "mov.b64 rc, {%6, %7};\n\t"
        "fma.rn.f32x2 rd, ra, rb, rc;\n\t"
        "mov.b64 {%0, %1}, rd;\n\t"
        "}"
        : "=f"(r.x), "=f"(r.y)
        : "f"(a.x), "f"(a.y), "f"(b.x), "f"(b.y), "f"(c.x), "f"(c.y));
    return r;
}

__device__ __forceinline__ float2 bflo2(unsigned u) {
    float f = __uint_as_float(u << 16);
    return make_float2(f, f);
}
__device__ __forceinline__ float2 bfhi2(unsigned u) {
    float f = __uint_as_float(u & 0xFFFF0000u);
    return make_float2(f, f);
}

__device__ __forceinline__ float tanh_hw(float x) {
    float y;
    asm("tanh.approx.f32 %0, %1;" : "=f"(y) : "f"(x));
    return y;
}
__device__ __forceinline__ float sigmf(float v) {
    return fmaf(0.5f, tanh_hw(0.5f * v), 0.5f);
}
__device__ __forceinline__ float softplusf(float v) {
    return fmaxf(v, 0.0f) + __logf(1.0f + __expf(-fabsf(v)));
}

__device__ __forceinline__ unsigned pack_bf16x2(float lo, float hi) {
    unsigned ulo = (unsigned)__bfloat16_as_ushort(__float2bfloat16_rn(lo));
    unsigned uhi = (unsigned)__bfloat16_as_ushort(__float2bfloat16_rn(hi));
    return (uhi << 16) | ulo;
}

// ---------- setup: repack weights ----------
__global__ void repack_weights(const float* __restrict__ Whh,
                               const float* __restrict__ Wih) {
    int idx = blockIdx.x * blockDim.x + threadIdx.x;
    if (idx < HH * JP) {            // -> g_Wbf [k][jp]
        int k = idx / JP, jp = idx % JP;
        int j0 = 2 * jp, j1 = 2 * jp + 1;
        uint4 w;
        w.x = pack_bf16x2(Whh[j0 * HH + k], Whh[(j0 + HH) * HH + k]);
        w.y = pack_bf16x2(Whh[j1 * HH + k], Whh[(j1 + HH) * HH + k]);
        w.z = pack_bf16x2(Whh[(j0 + 2 * HH) * HH + k],
                          Whh[(j1 + 2 * HH) * HH + k]);
        w.w = 0;
        g_Wbf[idx] = w;
    }
    if (idx < TT * GG) {            // -> g_Wih2[t][j]
        int t = idx / GG, j = idx % GG;
        g_Wih2[idx] = make_float2(Wih[j * (TT * 2) + 2 * t],
                                  Wih[j * (TT * 2) + 2 * t + 1]);
    }
}

// ---------- main fused recurrent kernel ----------
extern "C" __global__ void __launch_bounds__(NTH, 2)
r2p2_kernel(const float* __restrict__ stat,
            const float* __restrict__ init_v,
            const float* __restrict__ init_p,
            const float* __restrict__ zin,
            const float* __restrict__ b_ih,
            const float* __restrict__ b_hh,
            const float* __restrict__ W1,
            const float* __restrict__ b1,
            const float* __restrict__ W2,
            const float* __restrict__ b2,
            float* __restrict__ out) {
    extern __shared__ float smem[];
    float* s_gi = smem;                    // GG*TB   (layout [j][b])
    float* s_h  = s_gi + GG * TB;          // HH*TB   (layout [k][b])
    float* s_sp = s_h  + HH * TB;          // SDD*TB  (static proj + b1)
    float* s_o1 = s_sp + SDD * TB;         // SDD*TB
    float* s_o2 = s_o1 + SDD * TB;         // 6*TB
    unsigned* s_w1 = reinterpret_cast<unsigned*>(s_o2 + 6 * TB); // HH*40 u32 (bf16 W1h, padded)
    float* s_x  = reinterpret_cast<float*>(s_w1 + HH * 40);      // TB*2

    const int tid = threadIdx.x;
    const int b0  = blockIdx.x * TB;
    const bool actA = (tid < 300);
    const int jp = tid >> 2;       // j-pair 0..74
    const int j0 = 2 * jp;
    const int qq = tid & 3;        // quarter: float4 slots {2qq, 2qq+1}

    // Phase-C decomposition: tid = g*32 + bp*2 + kh
    const int c_g  = tid >> 5;          // m-group 0..9
    const int c_bp = (tid & 31) >> 1;   // batch pair 0..15
    const int c_kh = tid & 1;           // k half

    // ---- init: h = 0, gi = b_ih, s_proj = b1 + static @ W1_static^T; W1h->smem ----
    for (int idx = tid; idx < HH * TB; idx += NTH) s_h[idx] = 0.0f;
    for (int idx = tid; idx < GG * TB; idx += NTH) s_gi[idx] = b_ih[idx >> 5];
    for (int idx = tid; idx < SDD * TB; idx += NTH) {
        int m = idx >> 5, b = idx & 31;
        float acc = b1[m];
        const float* wrow = W1 + m * (HH + SDD) + HH;
        const float* st   = stat + (size_t)(b0 + b) * SDD;
        #pragma unroll 5
        for (int d = 0; d < SDD; ++d) acc = fmaf(wrow[d], st[d], acc);
        s_sp[idx] = acc;
    }
    // W1 hidden block -> smem bf16: [k][g<10][4 u32]; slot s<3 of group g holds
    // (W1[5g+2s][k], W1[5g+2s+1][k]); slot 2 hi and slot 3 are zero padding.
    for (int idx = tid; idx < HH * 40; idx += NTH) {
        int k = idx / 40, r = idx % 40;
        int g = r >> 2, s = r & 3;
        unsigned v = 0;
        if (s < 3) {
            int m0 = 5 * g + 2 * s;
            float lo = W1[m0 * (HH + SDD) + k];
            float hi = (2 * s + 1 < 5) ? W1[(m0 + 1) * (HH + SDD) + k] : 0.0f;
            v = pack_bf16x2(lo, hi);
        }
        s_w1[idx] = v;
    }

    float xp0 = 0.f, xp1 = 0.f, dx0 = 0.f, dx1 = 0.f;
    if (tid < TB) {
        size_t g = (size_t)(b0 + tid) * 2;
        xp0 = init_p[g]; xp1 = init_p[g + 1];
        dx0 = init_v[g]; dx1 = init_v[g + 1];
    }

    // hoisted gate biases for the 2 owned hidden units
    float bhr0 = 0.f, bhz0 = 0.f, bhn0 = 0.f;
    float bhr1 = 0.f, bhz1 = 0.f, bhn1 = 0.f;
    if (actA) {
        bhr0 = b_hh[j0];          bhr1 = b_hh[j0 + 1];
        bhz0 = b_hh[j0 + HH];     bhz1 = b_hh[j0 + 1 + HH];
        bhn0 = b_hh[j0 + 2 * HH]; bhn1 = b_hh[j0 + 1 + 2 * HH];
    }
    __syncthreads();

    const size_t SIG_OFF = (size_t)2 * TT * BB;
    const size_t X_OFF   = (size_t)6 * TT * BB;

    for (int t = 0; t < TT; ++t) {
        // ===== Phase A: thread = (j-pair, quarter): 6 gate rows x 8 lanes =====
        // bf16-packed weights (1 LDG.128/k) + depth-2 software pipeline.
        float2 aR[2][4], aZ[2][4], aN[2][4];
        if (actA) {
            #pragma unroll
            for (int jj = 0; jj < 2; ++jj)
                #pragma unroll
                for (int v = 0; v < 4; ++v) {
                    aR[jj][v] = make_float2(0.f, 0.f);
                    aZ[jj][v] = make_float2(0.f, 0.f);
                    aN[jj][v] = make_float2(0.f, 0.f);
                }
            const uint4* wp = g_Wbf + jp;
            const float4* hp4 = reinterpret_cast<const float4*>(s_h) + 2 * qq;

            auto consume = [&](uint4 w, const float4* hp) {
                float4 hv0 = hp[0];
                float4 hv1 = hp[1];
                float2 h00 = make_float2(hv0.x, hv0.y);
                float2 h01 = make_float2(hv0.z, hv0.w);
                float2 h10 = make_float2(hv1.x, hv1.y);
                float2 h11 = make_float2(hv1.z, hv1.w);
                float2 wr0 = bflo2(w.x);
                float2 wz0 = bfhi2(w.x);
                float2 wr1 = bflo2(w.y);
                float2 wz1 = bfhi2(w.y);
                float2 wn0 = bflo2(w.z);
                float2 wn1 = bfhi2(w.z);
                aR[0][0] = ffma2(h00, wr0, aR[0][0]);
                aR[0][1] = ffma2(h01, wr0, aR[0][1]);
                aR[0][2] = ffma2(h10, wr0, aR[0][2]);
                aR[0][3] = ffma2(h11, wr0, aR[0][3]);
                aZ[0][0] = ffma2(h00, wz0, aZ[0][0]);
                aZ[0][1] = ffma2(h01, wz0, aZ[0][1]);
                aZ[0][2] = ffma2(h10, wz0, aZ[0][2]);
                aZ[0][3] = ffma2(h11, wz0, aZ[0][3]);
                aN[0][0] = ffma2(h00, wn0, aN[0][0]);
                aN[0][1] = ffma2(h01, wn0, aN[0][1]);
                aN[0][2] = ffma2(h10, wn0, aN[0][2]);
                aN[0][3] = ffma2(h11, wn0, aN[0][3]);
                aR[1][0] = ffma2(h00, wr1, aR[1][0]);
                aR[1][1] = ffma2(h01, wr1, aR[1][1]);
                aR[1][2] = ffma2(h10, wr1, aR[1][2]);
                aR[1][3] = ffma2(h11, wr1, aR[1][3]);
                aZ[1][0] = ffma2(h00, wz1, aZ[1][0]);
                aZ[1][1] = ffma2(h01, wz1, aZ[1][1]);
                aZ[1][2] = ffma2(h10, wz1, aZ[1][2]);
                aZ[1][3] = ffma2(h11, wz1, aZ[1][3]);
                aN[1][0] = ffma2(h00, wn1, aN[1][0]);
                aN[1][1] = ffma2(h01, wn1, aN[1][1]);
                aN[1][2] = ffma2(h10, wn1, aN[1][2]);
                aN[1][3] = ffma2(h11, wn1, aN[1][3]);
            };

            uint4 wA = __ldg(wp);
            uint4 wB = __ldg(wp + JP);
            wp += 2 * JP;
            #pragma unroll 1
            for (int k = 0; k < HH - 2; k += 2) {
                uint4 wC = __ldg(wp);
                uint4 wD = __ldg(wp + JP);
                wp += 2 * JP;
                consume(wA, hp4);  hp4 += 8;
                consume(wB, hp4);  hp4 += 8;
                wA = wC;
                wB = wD;
            }
            consume(wA, hp4);  hp4 += 8;
            consume(wB, hp4);
        }
        __syncthreads();   // all reads of old h complete

        // ===== Phase B (fused E): gi += Wih(:,t-1)*x_{t-1}; GRU gates; h_new =====
        if (actA) {
            float2 wirA = make_float2(0.f, 0.f), wizA = wirA, winA = wirA;
            float2 wirB = wirA, wizB = wirA, winB = wirA;
            if (t > 0) {
                const float2* wt = g_Wih2 + (t - 1) * GG;
                wirA = __ldg(wt + j0);           wirB = __ldg(wt + j0 + 1);
                wizA = __ldg(wt + j0 + HH);      wizB = __ldg(wt + j0 + 1 + HH);
                winA = __ldg(wt + j0 + 2 * HH);  winB = __ldg(wt + j0 + 1 + 2 * HH);
            }
            float4* gi4 = reinterpret_cast<float4*>(s_gi);
            float4* h4 = reinterpret_cast<float4*>(s_h);
            const float4* sx4 = reinterpret_cast<const float4*>(s_x);
            #pragma unroll
            for (int jj = 0; jj < 2; ++jj) {
                int j = j0 + jj;
                float bhr = jj ? bhr1 : bhr0;
                float bhz = jj ? bhz1 : bhz0;
                float bhn = jj ? bhn1 : bhn0;
                float2 wir = jj ? wirB : wirA;
                float2 wiz = jj ? wizB : wizA;
                float2 win = jj ? winB : winA;
                #pragma unroll
                for (int s = 0; s < 2; ++s) {
                    int fq = 2 * qq + s;
                    float4 vr = gi4[(j) * 8 + fq];
                    float4 vz = gi4[(j + HH) * 8 + fq];
                    float4 vn = gi4[(j + 2 * HH) * 8 + fq];
                    if (t > 0) {
                        float4 xa = sx4[2 * fq];
                        float4 xb = sx4[2 * fq + 1];
                        vr.x = fmaf(wir.x, xa.x, fmaf(wir.y, xa.y, vr.x));
                        vr.y = fmaf(wir.x, xa.z, fmaf(wir.y, xa.w, vr.y));
                        vr.z = fmaf(wir.x, xb.x, fmaf(wir.y, xb.y, vr.z));
                        vr.w = fmaf(wir.x, xb.z, fmaf(wir.y, xb.w, vr.w));
                        vz.x = fmaf(wiz.x, xa.x, fmaf(wiz.y, xa.y, vz.x));
                        vz.y = fmaf(wiz.x, xa.z, fmaf(wiz.y, xa.w, vz.y));
                        vz.z = fmaf(wiz.x, xb.x, fmaf(wiz.y, xb.y, vz.z));
                        vz.w = fmaf(wiz.x, xb.z, fmaf(wiz.y, xb.w, vz.w));
                        vn.x = fmaf(win.x, xa.x, fmaf(win.y, xa.y, vn.x));
                        vn.y = fmaf(win.x, xa.z, fmaf(win.y, xa.w, vn.y));
                        vn.z = fmaf(win.x, xb.x, fmaf(win.y, xb.y, vn.z));
                        vn.w = fmaf(win.x, xb.z, fmaf(win.y, xb.w, vn.w));
                        gi4[(j) * 8 + fq]          = vr;
                        gi4[(j + HH) * 8 + fq]     = vz;
                        gi4[(j + 2 * HH) * 8 + fq] = vn;
                    }
                    float2 aR0 = aR[jj][2*s], aR1 = aR[jj][2*s+1];
                    float2 aZ0 = aZ[jj][2*s], aZ1 = aZ[jj][2*s+1];
                    float2 aN0 = aN[jj][2*s], aN1 = aN[jj][2*s+1];
                    float r0 = sigmf(vr.x + aR0.x + bhr);
                    float r1 = sigmf(vr.y + aR0.y + bhr);
                    float r2 = sigmf(vr.z + aR1.x + bhr);
                    float r3 = sigmf(vr.w + aR1.y + bhr);
                    float z0 = sigmf(vz.x + aZ0.x + bhz);
                    float z1 = sigmf(vz.y + aZ0.y + bhz);
                    float z2 = sigmf(vz.z + aZ1.x + bhz);
                    float z3 = sigmf(vz.w + aZ1.y + bhz);
                    float n0 = tanh_hw(fmaf(r0, aN0.x + bhn, vn.x));
                    float n1 = tanh_hw(fmaf(r1, aN0.y + bhn, vn.y));
                    float n2 = tanh_hw(fmaf(r2, aN1.x + bhn, vn.z));
                    float n3 = tanh_hw(fmaf(r3, aN1.y + bhn, vn.w));
                    float4 hold = h4[j * 8 + fq];
                    float4 hnew;
                    hnew.x = fmaf(z0, hold.x - n0, n0);
                    hnew.y = fmaf(z1, hold.y - n1, n1);
                    hnew.z = fmaf(z2, hold.z - n2, n2);
                    hnew.w = fmaf(z3, hold.w - n3, n3);
                    h4[j * 8 + fq] = hnew;
                }
            }
        }
        __syncthreads();

        // ===== Phase C: o1 = softplus(h_new @ W1h^T + s_proj) =====
        // thread = (m-group g of 5, batch pair bp, k-half kh); W1 bf16 from SMEM.
        {
            float2 acc0 = make_float2(0.f, 0.f);
            float2 acc1 = acc0, acc2 = acc0, acc3 = acc0, acc4 = acc0;
            const float2* hcol = reinterpret_cast<const float2*>(s_h)
                                 + c_kh * 75 * 16 + c_bp;
            const uint4* wb = reinterpret_cast<const uint4*>(s_w1)
                              + c_kh * 75 * 10 + c_g;
            #pragma unroll 3
            for (int kk = 0; kk < 75; ++kk) {
                float2 hv = hcol[kk * 16];
                uint4 w = wb[kk * 10];
                acc0 = ffma2(hv, bflo2(w.x), acc0);
                acc1 = ffma2(hv, bfhi2(w.x), acc1);
                acc2 = ffma2(hv, bflo2(w.y), acc2);
                acc3 = ffma2(hv, bfhi2(w.y), acc3);
                acc4 = ffma2(hv, bflo2(w.z), acc4);
            }
            acc0.x += __shfl_xor_sync(0xFFFFFFFF, acc0.x, 1);
            acc0.y += __shfl_xor_sync(0xFFFFFFFF, acc0.y, 1);
            acc1.x += __shfl_xor_sync(0xFFFFFFFF, acc1.x, 1);
            acc1.y += __shfl_xor_sync(0xFFFFFFFF, acc1.y, 1);
            acc2.x += __shfl_xor_sync(0xFFFFFFFF, acc2.x, 1);
            acc2.y += __shfl_xor_sync(0xFFFFFFFF, acc2.y, 1);
            acc3.x += __shfl_xor_sync(0xFFFFFFFF, acc3.x, 1);
            acc3.y += __shfl_xor_sync(0xFFFFFFFF, acc3.y, 1);
            acc4.x += __shfl_xor_sync(0xFFFFFFFF, acc4.x, 1);
            acc4.y += __shfl_xor_sync(0xFFFFFFFF, acc4.y, 1);
            if (c_kh == 0) {
                float2 accs[5] = {acc0, acc1, acc2, acc3, acc4};
                #pragma unroll
                for (int i = 0; i < 5; ++i) {
                    int m = 5 * c_g + i;
                    float2 sp = reinterpret_cast<const float2*>(s_sp)[m * 16 + c_bp];
                    s_o1[m * TB + 2 * c_bp]     = softplusf(accs[i].x + sp.x);
                    s_o1[m * TB + 2 * c_bp + 1] = softplusf(accs[i].y + sp.y);
                }
            }
        }
        __syncthreads();

        // ===== Phase D1: o2 = softplus(o1 @ W2^T + b2), 192 threads =====
        if (tid < 192) {
            int m = tid >> 5, b = tid & 31;
            float acc = b2[m];
            const float* w = W2 + m * SDD;
            #pragma unroll 5
            for (int k = 0; k < SDD; ++k)
                acc = fmaf(w[k], s_o1[k * TB + b], acc);
            s_o2[m * TB + b] = softplusf(acc);
        }
        __syncthreads();

        // ===== Phase D2: expm 2x2, x update, outputs (one thread per b) =====
        if (tid < TB) {
            const int b = tid;
            const int gb = b0 + b;
            float o20 = s_o2[0 * TB + b];
            float o21 = s_o2[1 * TB + b];
            float aS = 2.0f * s_o2[2 * TB + b];
            float bS = s_o2[3 * TB + b] + s_o2[4 * TB + b];
            float cS = 2.0f * s_o2[5 * TB + b];
            float half_tr   = 0.5f * (aS + cS);
            float half_diff = 0.5f * (aS - cS);
            float disc = sqrtf(fmaf(half_diff, half_diff, bS * bS));
            float d = fmaxf(disc, 1e-12f);
            float ed  = __expf(d);
            float edi = __fdividef(1.0f, ed);
            float sinhc = __fdividef(0.5f * (ed - edi), d);
            float coshd = 0.5f * (ed + edi);
            if (disc < 1e-12f) coshd = 1.0f;
            float scale = __expf(half_tr);
            float m00 = scale * fmaf(sinhc,  half_diff, coshd);
            float m11 = scale * fmaf(-sinhc, half_diff, coshd);
            float m01 = scale * (sinhc * bS);

            float mu0 = xp0 + dx0 + o20;
            float mu1 = xp1 + dx1 + o21;
            float2 zv = reinterpret_cast<const float2*>(zin)[(size_t)t * BB + gb];
            float x0 = fmaf(m00, zv.x, fmaf(m01, zv.y, mu0));
            float x1 = fmaf(m01, zv.x, fmaf(m11, zv.y, mu1));
            dx0 = x0 - xp0; dx1 = x1 - xp1;
            xp0 = x0;       xp1 = x1;

            reinterpret_cast<float2*>(out)[(size_t)t * BB + gb] = make_float2(mu0, mu1);
            reinterpret_cast<float4*>(out + SIG_OFF)[(size_t)t * BB + gb] =
                make_float4(m00, m01, m01, m11);
            reinterpret_cast<float2*>(out + X_OFF)[(size_t)t * BB + gb] = make_float2(x0, x1);
            s_x[2 * b]     = x0;
            s_x[2 * b + 1] = x1;
        }
        __syncthreads();
    }
}

extern "C" void kernel_launch(void* const* d_in, const int* in_sizes, int n_in,
                              void* d_out, int out_size) {
    const float* stat   = (const float*)d_in[0];
    const float* init_v = (const float*)d_in[1];
    const float* init_p = (const float*)d_in[2];
    const float* z      = (const float*)d_in[3];
    const float* W_ih   = (const float*)d_in[4];
    const float* W_hh   = (const float*)d_in[5];
    const float* b_ih   = (const float*)d_in[6];
    const float* b_hh   = (const float*)d_in[7];
    const float* W1     = (const float*)d_in[8];
    const float* b1     = (const float*)d_in[9];
    const float* W2     = (const float*)d_in[10];
    const float* b2     = (const float*)d_in[11];
    float* out = (float*)d_out;

    repack_weights<<<(TT * GG + 255) / 256, 256>>>(W_hh, W_ih);

    const size_t smem_bytes =
        (size_t)(GG * TB + HH * TB + SDD * TB * 2 + 6 * TB) * sizeof(float)
        + (size_t)HH * 40 * sizeof(unsigned)
        + (size_t)TB * 2 * sizeof(float);
    cudaFuncSetAttribute(r2p2_kernel,
                         cudaFuncAttributeMaxDynamicSharedMemorySize,
                         (int)smem_bytes);
    r2p2_kernel<<<BB / TB, NTH, smem_bytes>>>(
        stat, init_v, init_p, z, b_ih, b_hh, W1, b1, W2, b2, out);
}

// round 17
// speedup vs baseline: 1.4566x; 1.0184x over previous
#include <cuda_runtime.h>
#include <cuda_bf16.h>
#include <math.h>

#define BB   131072
#define TT   30
#define HH   150
#define GG   450      // 3*H
#define SDD  50
#define TB   32       // batch tile per CTA
#define NTH  320      // 10 warps; 300 active in GEMM phase
#define JP   75       // j-pairs

// Device scratch for repacked weights (allowed: __device__ globals).
__device__ uint4  g_Wbf [HH * JP];       // bf16: (wr0,wz0|wr1,wz1|wn0,wn1|pad) [k][jp]
__device__ float2 g_Wih2[TT * GG];       // [t][j] -> (W_ih[j,2t], W_ih[j,2t+1])

// ---------- packed fp32x2 FMA (sm_103a) ----------
__device__ __forceinline__ float2 ffma2(float2 a, float2 b, float2 c) {
    float2 r;
    asm("{\n\t"
        ".reg .b64 ra, rb, rc, rd;\n\t"
        "mov.b64 ra, {%2, %3};\n\t"
        "mov.b64 rb, {%4, %5};\n\t"
        "mov.b64 rc, {%6, %7};\n\t"
        "fma.rn.f32x2 rd, ra, rb, rc;\n\t"
        "mov.b64 {%0, %1}, rd;\n\t"
        "}"
        : "=f"(r.x), "=f"(r.y)
        : "f"(a.x), "f"(a.y), "f"(b.x), "f"(b.y), "f"(c.x), "f"(c.y));
    return r;
}

__device__ __forceinline__ float2 bflo2(unsigned u) {
    float f = __uint_as_float(u << 16);
    return make_float2(f, f);
}
__device__ __forceinline__ float2 bfhi2(unsigned u) {
    float f = __uint_as_float(u & 0xFFFF0000u);
    return make_float2(f, f);
}

__device__ __forceinline__ float tanh_hw(float x) {
    float y;
    asm("tanh.approx.f32 %0, %1;" : "=f"(y) : "f"(x));
    return y;
}
__device__ __forceinline__ float sigmf(float v) {
    return fmaf(0.5f, tanh_hw(0.5f * v), 0.5f);
}
__device__ __forceinline__ float softplusf(float v) {
    return fmaxf(v, 0.0f) + __logf(1.0f + __expf(-fabsf(v)));
}

__device__ __forceinline__ unsigned pack_bf16x2(float lo, float hi) {
    unsigned ulo = (unsigned)__bfloat16_as_ushort(__float2bfloat16_rn(lo));
    unsigned uhi = (unsigned)__bfloat16_as_ushort(__float2bfloat16_rn(hi));
    return (uhi << 16) | ulo;
}

// ---------- setup: repack weights ----------
__global__ void repack_weights(const float* __restrict__ Whh,
                               const float* __restrict__ Wih) {
    int idx = blockIdx.x * blockDim.x + threadIdx.x;
    if (idx < HH * JP) {            // -> g_Wbf [k][jp]
        int k = idx / JP, jp = idx % JP;
        int j0 = 2 * jp, j1 = 2 * jp + 1;
        uint4 w;
        w.x = pack_bf16x2(Whh[j0 * HH + k], Whh[(j0 + HH) * HH + k]);
        w.y = pack_bf16x2(Whh[j1 * HH + k], Whh[(j1 + HH) * HH + k]);
        w.z = pack_bf16x2(Whh[(j0 + 2 * HH) * HH + k],
                          Whh[(j1 + 2 * HH) * HH + k]);
        w.w = 0;
        g_Wbf[idx] = w;
    }
    if (idx < TT * GG) {            // -> g_Wih2[t][j]
        int t = idx / GG, j = idx % GG;
        g_Wih2[idx] = make_float2(Wih[j * (TT * 2) + 2 * t],
                                  Wih[j * (TT * 2) + 2 * t + 1]);
    }
}

// ---------- main fused recurrent kernel ----------
extern "C" __global__ void __launch_bounds__(NTH, 2)
r2p2_kernel(const float* __restrict__ stat,
            const float* __restrict__ init_v,
            const float* __restrict__ init_p,
            const float* __restrict__ zin,
            const float* __restrict__ b_ih,
            const float* __restrict__ b_hh,
            const float* __restrict__ W1,
            const float* __restrict__ b1,
            const float* __restrict__ W2,
            const float* __restrict__ b2,
            float* __restrict__ out) {
    extern __shared__ float smem[];
    float* s_gi = smem;                    // GG*TB   (layout [j][b])
    float* s_h  = s_gi + GG * TB;          // HH*TB   (layout [k][b])
    float* s_sp = s_h  + HH * TB;          // SDD*TB  (static proj + b1)
    float* s_o1 = s_sp + SDD * TB;         // SDD*TB
    float* s_o2 = s_o1 + SDD * TB;         // 6*TB
    unsigned* s_w1 = reinterpret_cast<unsigned*>(s_o2 + 6 * TB); // HH*40 u32 (bf16 W1h, padded)
    float* s_x  = reinterpret_cast<float*>(s_w1 + HH * 40);      // TB*2

    const int tid = threadIdx.x;
    const int b0  = blockIdx.x * TB;
    const bool actA = (tid < 300);
    const int jp = tid >> 2;       // j-pair 0..74
    const int j0 = 2 * jp;
    const int qq = tid & 3;        // quarter: float4 slots {2qq, 2qq+1}

    // Phase-C decomposition: tid = g*32 + bp*2 + kh
    const int c_g  = tid >> 5;          // m-group 0..9
    const int c_bp = (tid & 31) >> 1;   // batch pair 0..15
    const int c_kh = tid & 1;           // k half

    // ---- init: h = 0, gi = b_ih, s_proj = b1 + static @ W1_static^T; W1h->smem ----
    for (int idx = tid; idx < HH * TB; idx += NTH) s_h[idx] = 0.0f;
    for (int idx = tid; idx < GG * TB; idx += NTH) s_gi[idx] = b_ih[idx >> 5];
    for (int idx = tid; idx < SDD * TB; idx += NTH) {
        int m = idx >> 5, b = idx & 31;
        float acc = b1[m];
        const float* wrow = W1 + m * (HH + SDD) + HH;
        const float* st   = stat + (size_t)(b0 + b) * SDD;
        #pragma unroll 5
        for (int d = 0; d < SDD; ++d) acc = fmaf(wrow[d], st[d], acc);
        s_sp[idx] = acc;
    }
    // W1 hidden block -> smem bf16: [k][g<10][4 u32]; slot s<3 of group g holds
    // (W1[5g+2s][k], W1[5g+2s+1][k]); slot 2 hi and slot 3 are zero padding.
    for (int idx = tid; idx < HH * 40; idx += NTH) {
        int k = idx / 40, r = idx % 40;
        int g = r >> 2, s = r & 3;
        unsigned v = 0;
        if (s < 3) {
            int m0 = 5 * g + 2 * s;
            float lo = W1[m0 * (HH + SDD) + k];
            float hi = (2 * s + 1 < 5) ? W1[(m0 + 1) * (HH + SDD) + k] : 0.0f;
            v = pack_bf16x2(lo, hi);
        }
        s_w1[idx] = v;
    }

    float xp0 = 0.f, xp1 = 0.f, dx0 = 0.f, dx1 = 0.f;
    if (tid < TB) {
        size_t g = (size_t)(b0 + tid) * 2;
        xp0 = init_p[g]; xp1 = init_p[g + 1];
        dx0 = init_v[g]; dx1 = init_v[g + 1];
    }

    // hoisted gate biases for the 2 owned hidden units
    float bhr0 = 0.f, bhz0 = 0.f, bhn0 = 0.f;
    float bhr1 = 0.f, bhz1 = 0.f, bhn1 = 0.f;
    if (actA) {
        bhr0 = b_hh[j0];          bhr1 = b_hh[j0 + 1];
        bhz0 = b_hh[j0 + HH];     bhz1 = b_hh[j0 + 1 + HH];
        bhn0 = b_hh[j0 + 2 * HH]; bhn1 = b_hh[j0 + 1 + 2 * HH];
    }
    __syncthreads();

    const size_t SIG_OFF = (size_t)2 * TT * BB;
    const size_t X_OFF   = (size_t)6 * TT * BB;

    for (int t = 0; t < TT; ++t) {
        // ===== Phase A: thread = (j-pair, quarter): 6 gate rows x 8 lanes =====
        // bf16 weights (1 LDG.128/k, depth-2 pipeline) + depth-1 h-LDS pipeline.
        float2 aR[2][4], aZ[2][4], aN[2][4];
        if (actA) {
            #pragma unroll
            for (int jj = 0; jj < 2; ++jj)
                #pragma unroll
                for (int v = 0; v < 4; ++v) {
                    aR[jj][v] = make_float2(0.f, 0.f);
                    aZ[jj][v] = make_float2(0.f, 0.f);
                    aN[jj][v] = make_float2(0.f, 0.f);
                }
            const uint4* wp = g_Wbf + jp;
            const float4* hp4 = reinterpret_cast<const float4*>(s_h) + 2 * qq;

            auto consume = [&](uint4 w, float4 hv0, float4 hv1) {
                float2 h00 = make_float2(hv0.x, hv0.y);
                float2 h01 = make_float2(hv0.z, hv0.w);
                float2 h10 = make_float2(hv1.x, hv1.y);
                float2 h11 = make_float2(hv1.z, hv1.w);
                float2 wr0 = bflo2(w.x);
                float2 wz0 = bfhi2(w.x);
                float2 wr1 = bflo2(w.y);
                float2 wz1 = bfhi2(w.y);
                float2 wn0 = bflo2(w.z);
                float2 wn1 = bfhi2(w.z);
                aR[0][0] = ffma2(h00, wr0, aR[0][0]);
                aR[0][1] = ffma2(h01, wr0, aR[0][1]);
                aR[0][2] = ffma2(h10, wr0, aR[0][2]);
                aR[0][3] = ffma2(h11, wr0, aR[0][3]);
                aZ[0][0] = ffma2(h00, wz0, aZ[0][0]);
                aZ[0][1] = ffma2(h01, wz0, aZ[0][1]);
                aZ[0][2] = ffma2(h10, wz0, aZ[0][2]);
                aZ[0][3] = ffma2(h11, wz0, aZ[0][3]);
                aN[0][0] = ffma2(h00, wn0, aN[0][0]);
                aN[0][1] = ffma2(h01, wn0, aN[0][1]);
                aN[0][2] = ffma2(h10, wn0, aN[0][2]);
                aN[0][3] = ffma2(h11, wn0, aN[0][3]);
                aR[1][0] = ffma2(h00, wr1, aR[1][0]);
                aR[1][1] = ffma2(h01, wr1, aR[1][1]);
                aR[1][2] = ffma2(h10, wr1, aR[1][2]);
                aR[1][3] = ffma2(h11, wr1, aR[1][3]);
                aZ[1][0] = ffma2(h00, wz1, aZ[1][0]);
                aZ[1][1] = ffma2(h01, wz1, aZ[1][1]);
                aZ[1][2] = ffma2(h10, wz1, aZ[1][2]);
                aZ[1][3] = ffma2(h11, wz1, aZ[1][3]);
                aN[1][0] = ffma2(h00, wn1, aN[1][0]);
                aN[1][1] = ffma2(h01, wn1, aN[1][1]);
                aN[1][2] = ffma2(h10, wn1, aN[1][2]);
                aN[1][3] = ffma2(h11, wn1, aN[1][3]);
            };

            uint4 wA = __ldg(wp);
            uint4 wB = __ldg(wp + JP);
            wp += 2 * JP;
            float4 hA0 = hp4[0];
            float4 hA1 = hp4[1];
            hp4 += 8;
            #pragma unroll 1
            for (int k = 0; k < HH - 2; k += 2) {
                uint4 wC = __ldg(wp);
                uint4 wD = __ldg(wp + JP);
                wp += 2 * JP;
                float4 hB0 = hp4[0];
                float4 hB1 = hp4[1];
                hp4 += 8;
                consume(wA, hA0, hA1);
                float4 hN0 = hp4[0];
                float4 hN1 = hp4[1];
                hp4 += 8;
                consume(wB, hB0, hB1);
                wA = wC;   wB = wD;
                hA0 = hN0; hA1 = hN1;
            }
            float4 hB0 = hp4[0];
            float4 hB1 = hp4[1];
            consume(wA, hA0, hA1);
            consume(wB, hB0, hB1);
        }
        __syncthreads();   // all reads of old h complete; also orders s_x from D2(t-1)

        // ===== Phase B (fused E): gi += Wih(:,t-1)*x_{t-1}; GRU gates; h_new =====
        if (actA) {
            float2 wirA = make_float2(0.f, 0.f), wizA = wirA, winA = wirA;
            float2 wirB = wirA, wizB = wirA, winB = wirA;
            if (t > 0) {
                const float2* wt = g_Wih2 + (t - 1) * GG;
                wirA = __ldg(wt + j0);           wirB = __ldg(wt + j0 + 1);
                wizA = __ldg(wt + j0 + HH);      wizB = __ldg(wt + j0 + 1 + HH);
                winA = __ldg(wt + j0 + 2 * HH);  winB = __ldg(wt + j0 + 1 + 2 * HH);
            }
            float4* gi4 = reinterpret_cast<float4*>(s_gi);
            float4* h4 = reinterpret_cast<float4*>(s_h);
            const float4* sx4 = reinterpret_cast<const float4*>(s_x);
            #pragma unroll
            for (int jj = 0; jj < 2; ++jj) {
                int j = j0 + jj;
                float bhr = jj ? bhr1 : bhr0;
                float bhz = jj ? bhz1 : bhz0;
                float bhn = jj ? bhn1 : bhn0;
                float2 wir = jj ? wirB : wirA;
                float2 wiz = jj ? wizB : wizA;
                float2 win = jj ? winB : winA;
                #pragma unroll
                for (int s = 0; s < 2; ++s) {
                    int fq = 2 * qq + s;
                    float4 vr = gi4[(j) * 8 + fq];
                    float4 vz = gi4[(j + HH) * 8 + fq];
                    float4 vn = gi4[(j + 2 * HH) * 8 + fq];
                    if (t > 0) {
                        float4 xa = sx4[2 * fq];
                        float4 xb = sx4[2 * fq + 1];
                        vr.x = fmaf(wir.x, xa.x, fmaf(wir.y, xa.y, vr.x));
                        vr.y = fmaf(wir.x, xa.z, fmaf(wir.y, xa.w, vr.y));
                        vr.z = fmaf(wir.x, xb.x, fmaf(wir.y, xb.y, vr.z));
                        vr.w = fmaf(wir.x, xb.z, fmaf(wir.y, xb.w, vr.w));
                        vz.x = fmaf(wiz.x, xa.x, fmaf(wiz.y, xa.y, vz.x));
                        vz.y = fmaf(wiz.x, xa.z, fmaf(wiz.y, xa.w, vz.y));
                        vz.z = fmaf(wiz.x, xb.x, fmaf(wiz.y, xb.y, vz.z));
                        vz.w = fmaf(wiz.x, xb.z, fmaf(wiz.y, xb.w, vz.w));
                        vn.x = fmaf(win.x, xa.x, fmaf(win.y, xa.y, vn.x));
                        vn.y = fmaf(win.x, xa.z, fmaf(win.y, xa.w, vn.y));
                        vn.z = fmaf(win.x, xb.x, fmaf(win.y, xb.y, vn.z));
                        vn.w = fmaf(win.x, xb.z, fmaf(win.y, xb.w, vn.w));
                        gi4[(j) * 8 + fq]          = vr;
                        gi4[(j + HH) * 8 + fq]     = vz;
                        gi4[(j + 2 * HH) * 8 + fq] = vn;
                    }
                    float2 aR0 = aR[jj][2*s], aR1 = aR[jj][2*s+1];
                    float2 aZ0 = aZ[jj][2*s], aZ1 = aZ[jj][2*s+1];
                    float2 aN0 = aN[jj][2*s], aN1 = aN[jj][2*s+1];
                    float r0 = sigmf(vr.x + aR0.x + bhr);
                    float r1 = sigmf(vr.y + aR0.y + bhr);
                    float r2 = sigmf(vr.z + aR1.x + bhr);
                    float r3 = sigmf(vr.w + aR1.y + bhr);
                    float z0 = sigmf(vz.x + aZ0.x + bhz);
                    float z1 = sigmf(vz.y + aZ0.y + bhz);
                    float z2 = sigmf(vz.z + aZ1.x + bhz);
                    float z3 = sigmf(vz.w + aZ1.y + bhz);
                    float n0 = tanh_hw(fmaf(r0, aN0.x + bhn, vn.x));
                    float n1 = tanh_hw(fmaf(r1, aN0.y + bhn, vn.y));
                    float n2 = tanh_hw(fmaf(r2, aN1.x + bhn, vn.z));
                    float n3 = tanh_hw(fmaf(r3, aN1.y + bhn, vn.w));
                    float4 hold = h4[j * 8 + fq];
                    float4 hnew;
                    hnew.x = fmaf(z0, hold.x - n0, n0);
                    hnew.y = fmaf(z1, hold.y - n1, n1);
                    hnew.z = fmaf(z2, hold.z - n2, n2);
                    hnew.w = fmaf(z3, hold.w - n3, n3);
                    h4[j * 8 + fq] = hnew;
                }
            }
        }
        __syncthreads();

        // ===== Phase C: o1 = softplus(h_new @ W1h^T + s_proj) =====
        // thread = (m-group g of 5, batch pair bp, k-half kh); W1 bf16 from SMEM.
        {
            float2 acc0 = make_float2(0.f, 0.f);
            float2 acc1 = acc0, acc2 = acc0, acc3 = acc0, acc4 = acc0;
            const float2* hcol = reinterpret_cast<const float2*>(s_h)
                                 + c_kh * 75 * 16 + c_bp;
            const uint4* wb = reinterpret_cast<const uint4*>(s_w1)
                              + c_kh * 75 * 10 + c_g;
            #pragma unroll 3
            for (int kk = 0; kk < 75; ++kk) {
                float2 hv = hcol[kk * 16];
                uint4 w = wb[kk * 10];
                acc0 = ffma2(hv, bflo2(w.x), acc0);
                acc1 = ffma2(hv, bfhi2(w.x), acc1);
                acc2 = ffma2(hv, bflo2(w.y), acc2);
                acc3 = ffma2(hv, bfhi2(w.y), acc3);
                acc4 = ffma2(hv, bflo2(w.z), acc4);
            }
            acc0.x += __shfl_xor_sync(0xFFFFFFFF, acc0.x, 1);
            acc0.y += __shfl_xor_sync(0xFFFFFFFF, acc0.y, 1);
            acc1.x += __shfl_xor_sync(0xFFFFFFFF, acc1.x, 1);
            acc1.y += __shfl_xor_sync(0xFFFFFFFF, acc1.y, 1);
            acc2.x += __shfl_xor_sync(0xFFFFFFFF, acc2.x, 1);
            acc2.y += __shfl_xor_sync(0xFFFFFFFF, acc2.y, 1);
            acc3.x += __shfl_xor_sync(0xFFFFFFFF, acc3.x, 1);
            acc3.y += __shfl_xor_sync(0xFFFFFFFF, acc3.y, 1);
            acc4.x += __shfl_xor_sync(0xFFFFFFFF, acc4.x, 1);
            acc4.y += __shfl_xor_sync(0xFFFFFFFF, acc4.y, 1);
            if (c_kh == 0) {
                float2 accs[5] = {acc0, acc1, acc2, acc3, acc4};
                #pragma unroll
                for (int i = 0; i < 5; ++i) {
                    int m = 5 * c_g + i;
                    float2 sp = reinterpret_cast<const float2*>(s_sp)[m * 16 + c_bp];
                    float2 o;
                    o.x = softplusf(accs[i].x + sp.x);
                    o.y = softplusf(accs[i].y + sp.y);
                    reinterpret_cast<float2*>(s_o1)[m * 16 + c_bp] = o;
                }
            }
        }
        __syncthreads();

        // ===== Phase D1: o2 = softplus(o1 @ W2^T + b2), 192 threads =====
        if (tid < 192) {
            int m = tid >> 5, b = tid & 31;
            float acc = b2[m];
            const float* w = W2 + m * SDD;
            #pragma unroll 5
            for (int k = 0; k < SDD; ++k)
                acc = fmaf(w[k], s_o1[k * TB + b], acc);
            s_o2[m * TB + b] = softplusf(acc);
        }
        __syncthreads();

        // ===== Phase D2: expm 2x2, x update, outputs (one thread per b) =====
        // NOTE: no trailing sync — the post-A barrier of step t+1 orders s_x/s_o2
        // (D2 writers are program-ordered before their own A(t+1); all consumers
        // of s_x / writers of s_o2 sit behind >=1 subsequent barrier).
        if (tid < TB) {
            const int b = tid;
            const int gb = b0 + b;
            float o20 = s_o2[0 * TB + b];
            float o21 = s_o2[1 * TB + b];
            float aS = 2.0f * s_o2[2 * TB + b];
            float bS = s_o2[3 * TB + b] + s_o2[4 * TB + b];
            float cS = 2.0f * s_o2[5 * TB + b];
            float half_tr   = 0.5f * (aS + cS);
            float half_diff = 0.5f * (aS - cS);
            float disc = sqrtf(fmaf(half_diff, half_diff, bS * bS));
            float d = fmaxf(disc, 1e-12f);
            float ed  = __expf(d);
            float edi = __fdividef(1.0f, ed);
            float sinhc = __fdividef(0.5f * (ed - edi), d);
            float coshd = 0.5f * (ed + edi);
            if (disc < 1e-12f) coshd = 1.0f;
            float scale = __expf(half_tr);
            float m00 = scale * fmaf(sinhc,  half_diff, coshd);
            float m11 = scale * fmaf(-sinhc, half_diff, coshd);
            float m01 = scale * (sinhc * bS);

            float mu0 = xp0 + dx0 + o20;
            float mu1 = xp1 + dx1 + o21;
            float2 zv = reinterpret_cast<const float2*>(zin)[(size_t)t * BB + gb];
            float x0 = fmaf(m00, zv.x, fmaf(m01, zv.y, mu0));
            float x1 = fmaf(m01, zv.x, fmaf(m11, zv.y, mu1));
            dx0 = x0 - xp0; dx1 = x1 - xp1;
            xp0 = x0;       xp1 = x1;

            reinterpret_cast<float2*>(out)[(size_t)t * BB + gb] = make_float2(mu0, mu1);
            reinterpret_cast<float4*>(out + SIG_OFF)[(size_t)t * BB + gb] =
                make_float4(m00, m01, m01, m11);
            reinterpret_cast<float2*>(out + X_OFF)[(size_t)t * BB + gb] = make_float2(x0, x1);
            s_x[2 * b]     = x0;
            s_x[2 * b + 1] = x1;
        }
        // (sync removed — see note above)
    }
}

extern "C" void kernel_launch(void* const* d_in, const int* in_sizes, int n_in,
                              void* d_out, int out_size) {
    const float* stat   = (const float*)d_in[0];
    const float* init_v = (const float*)d_in[1];
    const float* init_p = (const float*)d_in[2];
    const float* z      = (const float*)d_in[3];
    const float* W_ih   = (const float*)d_in[4];
    const float* W_hh   = (const float*)d_in[5];
    const float* b_ih   = (const float*)d_in[6];
    const float* b_hh   = (const float*)d_in[7];
    const float* W1     = (const float*)d_in[8];
    const float* b1     = (const float*)d_in[9];
    const float* W2     = (const float*)d_in[10];
    const float* b2     = (const float*)d_in[11];
    float* out = (float*)d_out;

    repack_weights<<<(TT * GG + 255) / 256, 256>>>(W_hh, W_ih);

    const size_t smem_bytes =
        (size_t)(GG * TB + HH * TB + SDD * TB * 2 + 6 * TB) * sizeof(float)
        + (size_t)HH * 40 * sizeof(unsigned)
        + (size_t)TB * 2 * sizeof(float);
    cudaFuncSetAttribute(r2p2_kernel,
                         cudaFuncAttributeMaxDynamicSharedMemorySize,
                         (int)smem_bytes);
    r2p2_kernel<<<BB / TB, NTH, smem_bytes>>>(
        stat, init_v, init_p, z, b_ih, b_hh, W1, b1, W2, b2, out);
}